// round 11
// baseline (speedup 1.0000x reference)
#include <cuda_runtime.h>
#include <cuda_fp16.h>
#include <math.h>

#define Nn 100000
#define Ee 3200000
#define FIN 512
#define NHID 64
#define NCLS 40
#define KSTEPS 10

#define PROP_CO 6                       // co-resident CTAs per SM
#define PROP_BLOCKS (148 * PROP_CO)     // 888
#define PROP_THREADS 256
#define PROP_STEPS (KSTEPS - 1)         // steps 0..8 in the persistent kernel

// ---------------- scratch (static device globals — no allocation) ----------
__device__ float4 g_h [Nn * 10];        // teleport term fp32, [N][40]
__device__ uint4  g_yh[Nn * 5];         // h in fp16 (= y_0), [N][5 x 8 halfs]
__device__ uint4  g_ya[Nn * 5];         // scaled fp16 iterate ping
__device__ uint4  g_yb[Nn * 5];         // scaled fp16 iterate pong
__device__ float  g_x1[(size_t)Nn * NHID];  // layer-1 activations
__device__ int    g_counts[Nn];
__device__ int    g_rowptr[Nn + 1];
__device__ int    g_cursor[Nn];
__device__ int2   g_colval[Ee];         // interleaved {col, val-bits}
__device__ unsigned g_bar;              // persistent-kernel barrier counter

#define SCAN_BLK  1024
#define SCAN_NBLK ((Nn + SCAN_BLK - 1) / SCAN_BLK)   // 98
__device__ unsigned long long g_pub[SCAN_NBLK];      // packed {flag,sum}

// ---------------- fp16x8 helpers -------------------------------------------
__device__ __forceinline__ void fma8(float* a, float v, uint4 y)
{
    __half2 h0 = *reinterpret_cast<__half2*>(&y.x);
    __half2 h1 = *reinterpret_cast<__half2*>(&y.y);
    __half2 h2 = *reinterpret_cast<__half2*>(&y.z);
    __half2 h3 = *reinterpret_cast<__half2*>(&y.w);
    float2 f0 = __half22float2(h0), f1 = __half22float2(h1);
    float2 f2 = __half22float2(h2), f3 = __half22float2(h3);
    a[0] = fmaf(v, f0.x, a[0]); a[1] = fmaf(v, f0.y, a[1]);
    a[2] = fmaf(v, f1.x, a[2]); a[3] = fmaf(v, f1.y, a[3]);
    a[4] = fmaf(v, f2.x, a[4]); a[5] = fmaf(v, f2.y, a[5]);
    a[6] = fmaf(v, f3.x, a[6]); a[7] = fmaf(v, f3.y, a[7]);
}

__device__ __forceinline__ void unpack8(uint4 y, float* f)
{
    __half2 h0 = *reinterpret_cast<__half2*>(&y.x);
    __half2 h1 = *reinterpret_cast<__half2*>(&y.y);
    __half2 h2 = *reinterpret_cast<__half2*>(&y.z);
    __half2 h3 = *reinterpret_cast<__half2*>(&y.w);
    float2 f0 = __half22float2(h0), f1 = __half22float2(h1);
    float2 f2 = __half22float2(h2), f3 = __half22float2(h3);
    f[0] = f0.x; f[1] = f0.y; f[2] = f1.x; f[3] = f1.y;
    f[4] = f2.x; f[5] = f2.y; f[6] = f3.x; f[7] = f3.y;
}

__device__ __forceinline__ uint4 pack8(const float* f)
{
    __half2 h0 = __floats2half2_rn(f[0], f[1]);
    __half2 h1 = __floats2half2_rn(f[2], f[3]);
    __half2 h2 = __floats2half2_rn(f[4], f[5]);
    __half2 h3 = __floats2half2_rn(f[6], f[7]);
    uint4 r;
    r.x = *reinterpret_cast<unsigned*>(&h0);
    r.y = *reinterpret_cast<unsigned*>(&h1);
    r.z = *reinterpret_cast<unsigned*>(&h2);
    r.w = *reinterpret_cast<unsigned*>(&h3);
    return r;
}

// edge gather over fp16 rows: colval software prefetch, single 8-wide acc
// (8 rotating accumulators give >=8-issue reuse distance >> FMA latency;
//  the two LDGs per iter are address-independent and stay in flight)
__device__ __forceinline__ void gather8(const uint4* __restrict__ yin,
                                        int s, int e, int g, float* acc)
{
#pragma unroll
    for (int j = 0; j < 8; j++) acc[j] = 0.f;
    int i = s;
    int2 c0, c1;
    if (i + 2 <= e) {
        c0 = g_colval[i];
        c1 = g_colval[i + 1];
    }
    for (; i + 4 <= e; i += 2) {
        uint4 y0 = __ldg(&yin[(size_t)c0.x * 5 + g]);
        uint4 y1 = __ldg(&yin[(size_t)c1.x * 5 + g]);
        int2 n0 = g_colval[i + 2];
        int2 n1 = g_colval[i + 3];
        fma8(acc, __int_as_float(c0.y), y0);
        fma8(acc, __int_as_float(c1.y), y1);
        c0 = n0; c1 = n1;
    }
    if (i + 2 <= e) {
        uint4 y0 = __ldg(&yin[(size_t)c0.x * 5 + g]);
        uint4 y1 = __ldg(&yin[(size_t)c1.x * 5 + g]);
        fma8(acc, __int_as_float(c0.y), y0);
        fma8(acc, __int_as_float(c1.y), y1);
        i += 2;
    }
    if (i < e) {
        int2 ct = g_colval[i];
        uint4 y0 = __ldg(&yin[(size_t)ct.x * 5 + g]);
        fma8(acc, __int_as_float(ct.y), y0);
    }
}

// ---------------- layer 1: x1 = relu(X@W1 + b1) via tf32 mma ---------------
// cvt.rna at fragment load (round-to-nearest tf32 — accuracy-critical).
#define L1_BM 128
#define L1_BK 16
#define NTILE (FIN / L1_BK)   // 32
#define LDA   20
#define LDB   72

__device__ __forceinline__ unsigned f2tf32(float f) {
    unsigned r;
    asm("cvt.rna.tf32.f32 %0, %1;" : "=r"(r) : "f"(f));
    return r;
}

__device__ __forceinline__ void mma_tf32(float* c, unsigned a0, unsigned a1,
                                         unsigned a2, unsigned a3,
                                         unsigned b0, unsigned b1) {
    asm volatile(
        "mma.sync.aligned.m16n8k8.row.col.f32.tf32.tf32.f32 "
        "{%0,%1,%2,%3}, {%4,%5,%6,%7}, {%8,%9}, {%0,%1,%2,%3};\n"
        : "+f"(c[0]), "+f"(c[1]), "+f"(c[2]), "+f"(c[3])
        : "r"(a0), "r"(a1), "r"(a2), "r"(a3), "r"(b0), "r"(b1));
}

__device__ __forceinline__ void cp16(float* smem_dst, const float* gsrc, bool pred) {
    unsigned saddr = (unsigned)__cvta_generic_to_shared(smem_dst);
    int sz = pred ? 16 : 0;
    asm volatile("cp.async.cg.shared.global [%0], [%1], 16, %2;\n"
                 :: "r"(saddr), "l"(gsrc), "r"(sz));
}

__global__ __launch_bounds__(256, 3)
void mlp1_kernel(const float* __restrict__ feat,
                 const float* __restrict__ W1, const float* __restrict__ b1)
{
    __shared__ __align__(16) float As[3][L1_BM * LDA];
    __shared__ __align__(16) float Bs[3][L1_BK * LDB];

    const int tid    = threadIdx.x;
    const int lane   = tid & 31;
    const int warp   = tid >> 5;
    const int warp_m = warp & 3;
    const int warp_n = warp >> 2;
    const int gid    = lane >> 2;
    const int tig    = lane & 3;
    const int row0   = blockIdx.x * L1_BM;

    const int am0 = tid >> 2;
    const int ac0 = tid & 3;
    const int am1 = (tid + 256) >> 2;
    const int bk  = tid >> 4;
    const int bn  = tid & 15;

    float acc[2][4][4];
#pragma unroll
    for (int mi = 0; mi < 2; mi++)
#pragma unroll
        for (int ni = 0; ni < 4; ni++)
#pragma unroll
            for (int q = 0; q < 4; q++) acc[mi][ni][q] = 0.f;

    auto stage = [&](int t) {
        int buf = t % 3;
        int k0 = t * L1_BK;
        cp16(&As[buf][am0 * LDA + ac0 * 4],
             &feat[(size_t)(row0 + am0) * FIN + k0 + ac0 * 4], row0 + am0 < Nn);
        cp16(&As[buf][am1 * LDA + ac0 * 4],
             &feat[(size_t)(row0 + am1) * FIN + k0 + ac0 * 4], row0 + am1 < Nn);
        cp16(&Bs[buf][bk * LDB + bn * 4],
             &W1[(size_t)(k0 + bk) * NHID + bn * 4], true);
        asm volatile("cp.async.commit_group;\n");
    };

    stage(0);
    stage(1);

    for (int t = 0; t < NTILE; t++) {
        if (t + 2 < NTILE) {
            stage(t + 2);
            asm volatile("cp.async.wait_group 2;\n");
        } else if (t + 1 < NTILE) {
            asm volatile("cp.async.wait_group 1;\n");
        } else {
            asm volatile("cp.async.wait_group 0;\n");
        }
        __syncthreads();

        const float* A = As[t % 3];
        const float* B = Bs[t % 3];
#pragma unroll
        for (int kk = 0; kk < L1_BK; kk += 8) {
            unsigned a[2][4], b[4][2];
#pragma unroll
            for (int mi = 0; mi < 2; mi++) {
                int m0 = warp_m * 32 + mi * 16;
                a[mi][0] = f2tf32(A[(m0 + gid)     * LDA + kk + tig]);
                a[mi][1] = f2tf32(A[(m0 + 8 + gid) * LDA + kk + tig]);
                a[mi][2] = f2tf32(A[(m0 + gid)     * LDA + kk + 4 + tig]);
                a[mi][3] = f2tf32(A[(m0 + 8 + gid) * LDA + kk + 4 + tig]);
            }
#pragma unroll
            for (int ni = 0; ni < 4; ni++) {
                int n0 = warp_n * 32 + ni * 8;
                b[ni][0] = f2tf32(B[(kk + tig)     * LDB + n0 + gid]);
                b[ni][1] = f2tf32(B[(kk + 4 + tig) * LDB + n0 + gid]);
            }
#pragma unroll
            for (int mi = 0; mi < 2; mi++)
#pragma unroll
                for (int ni = 0; ni < 4; ni++)
                    mma_tf32(acc[mi][ni], a[mi][0], a[mi][1], a[mi][2], a[mi][3],
                             b[ni][0], b[ni][1]);
        }
        __syncthreads();
    }

#pragma unroll
    for (int mi = 0; mi < 2; mi++) {
        int rbase = row0 + warp_m * 32 + mi * 16 + gid;
#pragma unroll
        for (int ni = 0; ni < 4; ni++) {
            int col = warp_n * 32 + ni * 8 + 2 * tig;
            float bb0 = __ldg(&b1[col]);
            float bb1 = __ldg(&b1[col + 1]);
            if (rbase < Nn) {
                float2 v;
                v.x = fmaxf(acc[mi][ni][0] + bb0, 0.f);
                v.y = fmaxf(acc[mi][ni][1] + bb1, 0.f);
                *(float2*)&g_x1[(size_t)rbase * NHID + col] = v;
            }
            if (rbase + 8 < Nn) {
                float2 v;
                v.x = fmaxf(acc[mi][ni][2] + bb0, 0.f);
                v.y = fmaxf(acc[mi][ni][3] + bb1, 0.f);
                *(float2*)&g_x1[(size_t)(rbase + 8) * NHID + col] = v;
            }
        }
    }
}

// ---------------- layer 2: h = x1 @ W2 + b2 (writes fp32 h AND fp16 y_0) ---
__global__ __launch_bounds__(256)
void mlp2_kernel(const float* __restrict__ W2, const float* __restrict__ b2)
{
    __shared__ float W2s[NHID * NCLS];
    __shared__ float b2s[NCLS];
    int tid = threadIdx.x;
    for (int i = tid; i < NHID * NCLS; i += 256) W2s[i] = W2[i];
    if (tid < NCLS) b2s[tid] = b2[tid];
    __syncthreads();

    int row = blockIdx.x * blockDim.x + tid;
    if (row >= Nn) return;

    float out[NCLS];
#pragma unroll
    for (int c = 0; c < NCLS; c++) out[c] = b2s[c];
    const float* xr = &g_x1[(size_t)row * NHID];
#pragma unroll 4
    for (int k0 = 0; k0 < NHID; k0 += 4) {
        float4 xv = *(const float4*)&xr[k0];
        float xs[4] = {xv.x, xv.y, xv.z, xv.w};
#pragma unroll
        for (int kk = 0; kk < 4; kk++)
#pragma unroll
            for (int c = 0; c < NCLS; c++)
                out[c] = fmaf(xs[kk], W2s[(k0 + kk) * NCLS + c], out[c]);
    }
    float4* hp = g_h + (size_t)row * 10;
#pragma unroll
    for (int q = 0; q < 10; q++)
        hp[q] = make_float4(out[4*q], out[4*q+1], out[4*q+2], out[4*q+3]);
    uint4* yh = g_yh + (size_t)row * 5;
#pragma unroll
    for (int q = 0; q < 5; q++)
        yh[q] = pack8(&out[8 * q]);
}

// ---------------- CSR build ------------------------------------------------
__global__ void zero_kernel()
{
    int i = blockIdx.x * blockDim.x + threadIdx.x;
    if (i < Nn) g_counts[i] = 0;
    if (i < SCAN_NBLK) g_pub[i] = 0ull;
    if (i == 0) g_bar = 0u;
}

__global__ void hist_kernel(const int* __restrict__ rows)
{
    int j = blockIdx.x * blockDim.x + threadIdx.x;
    if (j < Ee / 4) {
        int4 r = ((const int4*)rows)[j];
        atomicAdd(&g_counts[r.x], 1);
        atomicAdd(&g_counts[r.y], 1);
        atomicAdd(&g_counts[r.z], 1);
        atomicAdd(&g_counts[r.w], 1);
    }
}

__global__ __launch_bounds__(SCAN_BLK)
void scan_kernel()
{
    __shared__ int swarp[32];
    __shared__ int s_prefix;
    __shared__ int s_total;

    const int b = blockIdx.x;
    const int t = threadIdx.x;
    const int lane = t & 31, wid = t >> 5;
    const int i = b * SCAN_BLK + t;

    int v = (i < Nn) ? g_counts[i] : 0;
    int incl = v;
#pragma unroll
    for (int off = 1; off < 32; off <<= 1) {
        int u = __shfl_up_sync(0xffffffffu, incl, off);
        if (lane >= off) incl += u;
    }
    if (lane == 31) swarp[wid] = incl;
    __syncthreads();
    if (wid == 0) {
        int w = swarp[lane];
        int wi = w;
#pragma unroll
        for (int off = 1; off < 32; off <<= 1) {
            int u = __shfl_up_sync(0xffffffffu, wi, off);
            if (lane >= off) wi += u;
        }
        swarp[lane] = wi - w;
        if (lane == 31) {
            int S = wi;
            s_total = S;
            if (b == 0) {
                atomicExch(&g_pub[0], (2ull << 32) | (unsigned)S);
                s_prefix = 0;
            } else {
                atomicExch(&g_pub[b], (1ull << 32) | (unsigned)S);
                long long run = 0;
                int p = b - 1;
                while (true) {
                    unsigned long long u =
                        *((volatile unsigned long long*)&g_pub[p]);
                    unsigned f = (unsigned)(u >> 32);
                    if (f == 2u) { run += (int)(unsigned)u; break; }
                    if (f == 1u) { run += (int)(unsigned)u; p--; }
                }
                atomicExch(&g_pub[b], (2ull << 32) | (unsigned)(run + S));
                s_prefix = (int)run;
            }
        }
    }
    __syncthreads();
    int pref = s_prefix;
    if (i < Nn) {
        int r = incl - v + swarp[wid] + pref;
        g_rowptr[i] = r;
        g_cursor[i] = r;
    }
    if (b == SCAN_NBLK - 1 && t == 0)
        g_rowptr[Nn] = pref + s_total;
}

__global__ void scatter_kernel(const int* __restrict__ rows,
                               const int* __restrict__ cols,
                               const float* __restrict__ vals)
{
    int j = blockIdx.x * blockDim.x + threadIdx.x;
    if (j < Ee / 4) {
        int4   r = ((const int4*)rows)[j];
        int4   c = ((const int4*)cols)[j];
        float4 v = ((const float4*)vals)[j];
        int p;
        p = atomicAdd(&g_cursor[r.x], 1); g_colval[p] = make_int2(c.x, __float_as_int(v.x));
        p = atomicAdd(&g_cursor[r.y], 1); g_colval[p] = make_int2(c.y, __float_as_int(v.y));
        p = atomicAdd(&g_cursor[r.z], 1); g_colval[p] = make_int2(c.z, __float_as_int(v.z));
        p = atomicAdd(&g_cursor[r.w], 1); g_colval[p] = make_int2(c.w, __float_as_int(v.w));
    }
}

// ---------------- persistent propagation: steps 0..8, scaled fp16 ----------
// y_{s+1} = (0.9/16) * A * y_s + (0.1/16^{s+1}) * h
__global__ __launch_bounds__(PROP_THREADS, PROP_CO)
void prop_persist_kernel()
{
    const int nthreads = PROP_BLOCKS * PROP_THREADS;
    const int tid0 = blockIdx.x * PROP_THREADS + threadIdx.x;
    const float W = 0.9f / 16.0f;

    for (int s = 0; s < PROP_STEPS; s++) {
        const uint4* __restrict__ yin =
            (s == 0) ? g_yh : ((s & 1) ? g_ya : g_yb);
        uint4* __restrict__ yout = (s & 1) ? g_yb : g_ya;
        const float hc = ldexpf(0.1f, -4 * (s + 1));   // exact 2^-4(s+1) scaling

        for (int t = tid0; t < Nn * 5; t += nthreads) {
            int node = t / 5;
            int g    = t - node * 5;
            float acc[8];
            gather8(yin, g_rowptr[node], g_rowptr[node + 1], g, acc);
            float hf[8];
            unpack8(g_yh[t], hf);
            float o[8];
#pragma unroll
            for (int j = 0; j < 8; j++)
                o[j] = fmaf(W, acc[j], hc * hf[j]);
            yout[t] = pack8(o);
        }

        __threadfence();
        __syncthreads();
        if (threadIdx.x == 0) {
            atomicAdd(&g_bar, 1u);
            unsigned target = (unsigned)(s + 1) * PROP_BLOCKS;
            while (*((volatile unsigned*)&g_bar) < target)
                __nanosleep(64);
        }
        __syncthreads();
        __threadfence();
    }
}

// ---------------- final step (unscale) + fused log_softmax ------------------
__global__ __launch_bounds__(320)
void prop_last_kernel(float* __restrict__ out)
{
    __shared__ float red[320];
    __shared__ float rlse[64];

    const int lt = threadIdx.x;
    const int t  = blockIdx.x * 320 + lt;
    const int node = t / 5;
    const int g    = t - node * 5;
    const int ln   = lt / 5;
    const bool valid = node < Nn;

    float o[8];
    if (valid) {
        float acc[8];
        gather8(g_ya, g_rowptr[node], g_rowptr[node + 1], g, acc);
        const float FINW = 0.9f * 68719476736.0f;   // 0.9 * 16^9
        float4 h0 = g_h[node * 10 + g * 2];
        float4 h1 = g_h[node * 10 + g * 2 + 1];
        float hv[8] = {h0.x, h0.y, h0.z, h0.w, h1.x, h1.y, h1.z, h1.w};
#pragma unroll
        for (int j = 0; j < 8; j++)
            o[j] = fmaf(FINW, acc[j], 0.1f * hv[j]);
    } else {
#pragma unroll
        for (int j = 0; j < 8; j++) o[j] = -INFINITY;
    }

    float lm = o[0];
#pragma unroll
    for (int j = 1; j < 8; j++) lm = fmaxf(lm, o[j]);
    red[lt] = lm;
    __syncthreads();
    if (g == 0) {
        float m = red[ln * 5];
#pragma unroll
        for (int q = 1; q < 5; q++) m = fmaxf(m, red[ln * 5 + q]);
        rlse[ln] = m;
    }
    __syncthreads();
    float m = rlse[ln];

    float s8 = 0.f;
    if (valid) {
#pragma unroll
        for (int j = 0; j < 8; j++) s8 += expf(o[j] - m);
    }
    __syncthreads();
    red[lt] = s8;
    __syncthreads();
    if (g == 0) {
        float s = red[ln * 5];
#pragma unroll
        for (int q = 1; q < 5; q++) s += red[ln * 5 + q];
        rlse[ln] = m + logf(s);
    }
    __syncthreads();

    if (valid) {
        float lse = rlse[ln];
        float4 r0 = make_float4(o[0]-lse, o[1]-lse, o[2]-lse, o[3]-lse);
        float4 r1 = make_float4(o[4]-lse, o[5]-lse, o[6]-lse, o[7]-lse);
        ((float4*)out)[node * 10 + g * 2]     = r0;
        ((float4*)out)[node * 10 + g * 2 + 1] = r1;
    }
}

// ---------------- launch ---------------------------------------------------
static cudaStream_t get_side_stream()
{
    static cudaStream_t s = []() {
        cudaStream_t st;
        cudaStreamCreateWithFlags(&st, cudaStreamNonBlocking);
        return st;
    }();
    return s;
}
static cudaEvent_t get_ev(int which)
{
    static cudaEvent_t e0 = []() {
        cudaEvent_t e; cudaEventCreateWithFlags(&e, cudaEventDisableTiming); return e;
    }();
    static cudaEvent_t e1 = []() {
        cudaEvent_t e; cudaEventCreateWithFlags(&e, cudaEventDisableTiming); return e;
    }();
    return which ? e1 : e0;
}

extern "C" void kernel_launch(void* const* d_in, const int* in_sizes, int n_in,
                              void* d_out, int out_size)
{
    const float* feat = (const float*)d_in[0];
    const int*   ei   = (const int*)  d_in[1];
    const float* ev   = (const float*)d_in[2];
    const float* W1   = (const float*)d_in[3];
    const float* b1   = (const float*)d_in[4];
    const float* W2   = (const float*)d_in[5];
    const float* b2   = (const float*)d_in[6];
    const int* rows = ei;
    const int* cols = ei + Ee;

    cudaStream_t s2 = get_side_stream();
    cudaEvent_t eva = get_ev(0), evb = get_ev(1);

    cudaEventRecord(eva, 0);
    cudaStreamWaitEvent(s2, eva, 0);

    // side stream: CSR build chain
    zero_kernel<<<(Nn + 255) / 256, 256, 0, s2>>>();                 // 1
    hist_kernel<<<(Ee / 4 + 255) / 256, 256, 0, s2>>>(rows);         // 2
    scan_kernel<<<SCAN_NBLK, SCAN_BLK, 0, s2>>>();                   // 3

    // main stream: MLP chain (launch 4 = mlp1, profiled)
    mlp1_kernel<<<(Nn + L1_BM - 1) / L1_BM, 256>>>(feat, W1, b1);    // 4

    scatter_kernel<<<(Ee / 4 + 255) / 256, 256, 0, s2>>>(rows, cols, ev);  // 5

    mlp2_kernel<<<(Nn + 255) / 256, 256>>>(W2, b2);                  // 6

    cudaEventRecord(evb, s2);
    cudaStreamWaitEvent(0, evb, 0);

    // steps 0..8 persistent (scaled fp16, 6 CTAs/SM)
    prop_persist_kernel<<<PROP_BLOCKS, PROP_THREADS>>>();

    // final step (unscale) + log_softmax
    prop_last_kernel<<<(Nn * 5 + 319) / 320, 320>>>((float*)d_out);
}

// round 12
// speedup vs baseline: 1.0633x; 1.0633x over previous
#include <cuda_runtime.h>
#include <cuda_fp16.h>
#include <math.h>

#define Nn 100000
#define Ee 3200000
#define FIN 512
#define NHID 64
#define NCLS 40
#define KSTEPS 10

#define PROP_CO 5                       // co-resident CTAs per SM (reg cap 51)
#define PROP_BLOCKS (148 * PROP_CO)     // 740
#define PROP_THREADS 256
#define PROP_STEPS (KSTEPS - 1)         // steps 0..8 in the persistent kernel

// ---------------- scratch (static device globals — no allocation) ----------
__device__ float4 g_h [Nn * 10];        // teleport term fp32, [N][40]
__device__ uint4  g_yh[Nn * 5];         // h in fp16 (= y_0), [N][5 x 8 halfs]
__device__ uint4  g_ya[Nn * 5];         // scaled fp16 iterate ping
__device__ uint4  g_yb[Nn * 5];         // scaled fp16 iterate pong
__device__ float  g_x1[(size_t)Nn * NHID];  // layer-1 activations
__device__ int    g_counts[Nn];
__device__ int    g_rowptr[Nn + 1];
__device__ int    g_cursor[Nn];
__device__ int2   g_colval[Ee];         // interleaved {col, val-bits}
__device__ unsigned g_bar;              // persistent-kernel barrier counter

#define SCAN_BLK  1024
#define SCAN_NBLK ((Nn + SCAN_BLK - 1) / SCAN_BLK)   // 98
__device__ unsigned long long g_pub[SCAN_NBLK];      // packed {flag,sum}

// ---------------- fp16x8 helpers -------------------------------------------
__device__ __forceinline__ void fma8(float* a, float v, uint4 y)
{
    __half2 h0 = *reinterpret_cast<__half2*>(&y.x);
    __half2 h1 = *reinterpret_cast<__half2*>(&y.y);
    __half2 h2 = *reinterpret_cast<__half2*>(&y.z);
    __half2 h3 = *reinterpret_cast<__half2*>(&y.w);
    float2 f0 = __half22float2(h0), f1 = __half22float2(h1);
    float2 f2 = __half22float2(h2), f3 = __half22float2(h3);
    a[0] = fmaf(v, f0.x, a[0]); a[1] = fmaf(v, f0.y, a[1]);
    a[2] = fmaf(v, f1.x, a[2]); a[3] = fmaf(v, f1.y, a[3]);
    a[4] = fmaf(v, f2.x, a[4]); a[5] = fmaf(v, f2.y, a[5]);
    a[6] = fmaf(v, f3.x, a[6]); a[7] = fmaf(v, f3.y, a[7]);
}

__device__ __forceinline__ void unpack8(uint4 y, float* f)
{
    __half2 h0 = *reinterpret_cast<__half2*>(&y.x);
    __half2 h1 = *reinterpret_cast<__half2*>(&y.y);
    __half2 h2 = *reinterpret_cast<__half2*>(&y.z);
    __half2 h3 = *reinterpret_cast<__half2*>(&y.w);
    float2 f0 = __half22float2(h0), f1 = __half22float2(h1);
    float2 f2 = __half22float2(h2), f3 = __half22float2(h3);
    f[0] = f0.x; f[1] = f0.y; f[2] = f1.x; f[3] = f1.y;
    f[4] = f2.x; f[5] = f2.y; f[6] = f3.x; f[7] = f3.y;
}

__device__ __forceinline__ uint4 pack8(const float* f)
{
    __half2 h0 = __floats2half2_rn(f[0], f[1]);
    __half2 h1 = __floats2half2_rn(f[2], f[3]);
    __half2 h2 = __floats2half2_rn(f[4], f[5]);
    __half2 h3 = __floats2half2_rn(f[6], f[7]);
    uint4 r;
    r.x = *reinterpret_cast<unsigned*>(&h0);
    r.y = *reinterpret_cast<unsigned*>(&h1);
    r.z = *reinterpret_cast<unsigned*>(&h2);
    r.w = *reinterpret_cast<unsigned*>(&h3);
    return r;
}

// edge gather over fp16 rows: dual accumulator + colval software prefetch
// (R10 best-measured form; probe measured 40 regs — fits CO=5 cap of 51)
__device__ __forceinline__ void gather8(const uint4* __restrict__ yin,
                                        int s, int e, int g, float* acc)
{
    float a[8] = {0.f,0.f,0.f,0.f,0.f,0.f,0.f,0.f};
    float b[8] = {0.f,0.f,0.f,0.f,0.f,0.f,0.f,0.f};
    int i = s;
    int2 c0, c1;
    if (i + 2 <= e) {
        c0 = g_colval[i];
        c1 = g_colval[i + 1];
    }
    for (; i + 4 <= e; i += 2) {
        uint4 y0 = __ldg(&yin[(size_t)c0.x * 5 + g]);
        uint4 y1 = __ldg(&yin[(size_t)c1.x * 5 + g]);
        int2 n0 = g_colval[i + 2];
        int2 n1 = g_colval[i + 3];
        fma8(a, __int_as_float(c0.y), y0);
        fma8(b, __int_as_float(c1.y), y1);
        c0 = n0; c1 = n1;
    }
    if (i + 2 <= e) {
        uint4 y0 = __ldg(&yin[(size_t)c0.x * 5 + g]);
        uint4 y1 = __ldg(&yin[(size_t)c1.x * 5 + g]);
        fma8(a, __int_as_float(c0.y), y0);
        fma8(b, __int_as_float(c1.y), y1);
        i += 2;
    }
    if (i < e) {
        int2 ct = g_colval[i];
        uint4 y0 = __ldg(&yin[(size_t)ct.x * 5 + g]);
        fma8(a, __int_as_float(ct.y), y0);
    }
#pragma unroll
    for (int j = 0; j < 8; j++) acc[j] = a[j] + b[j];
}

// ---------------- layer 1: x1 = relu(X@W1 + b1) via tf32 mma ---------------
// cvt.rna at fragment load (round-to-nearest tf32 — accuracy-critical).
#define L1_BM 128
#define L1_BK 16
#define NTILE (FIN / L1_BK)   // 32
#define LDA   20
#define LDB   72

__device__ __forceinline__ unsigned f2tf32(float f) {
    unsigned r;
    asm("cvt.rna.tf32.f32 %0, %1;" : "=r"(r) : "f"(f));
    return r;
}

__device__ __forceinline__ void mma_tf32(float* c, unsigned a0, unsigned a1,
                                         unsigned a2, unsigned a3,
                                         unsigned b0, unsigned b1) {
    asm volatile(
        "mma.sync.aligned.m16n8k8.row.col.f32.tf32.tf32.f32 "
        "{%0,%1,%2,%3}, {%4,%5,%6,%7}, {%8,%9}, {%0,%1,%2,%3};\n"
        : "+f"(c[0]), "+f"(c[1]), "+f"(c[2]), "+f"(c[3])
        : "r"(a0), "r"(a1), "r"(a2), "r"(a3), "r"(b0), "r"(b1));
}

__device__ __forceinline__ void cp16(float* smem_dst, const float* gsrc, bool pred) {
    unsigned saddr = (unsigned)__cvta_generic_to_shared(smem_dst);
    int sz = pred ? 16 : 0;
    asm volatile("cp.async.cg.shared.global [%0], [%1], 16, %2;\n"
                 :: "r"(saddr), "l"(gsrc), "r"(sz));
}

__global__ __launch_bounds__(256, 3)
void mlp1_kernel(const float* __restrict__ feat,
                 const float* __restrict__ W1, const float* __restrict__ b1)
{
    __shared__ __align__(16) float As[3][L1_BM * LDA];
    __shared__ __align__(16) float Bs[3][L1_BK * LDB];

    const int tid    = threadIdx.x;
    const int lane   = tid & 31;
    const int warp   = tid >> 5;
    const int warp_m = warp & 3;
    const int warp_n = warp >> 2;
    const int gid    = lane >> 2;
    const int tig    = lane & 3;
    const int row0   = blockIdx.x * L1_BM;

    const int am0 = tid >> 2;
    const int ac0 = tid & 3;
    const int am1 = (tid + 256) >> 2;
    const int bk  = tid >> 4;
    const int bn  = tid & 15;

    float acc[2][4][4];
#pragma unroll
    for (int mi = 0; mi < 2; mi++)
#pragma unroll
        for (int ni = 0; ni < 4; ni++)
#pragma unroll
            for (int q = 0; q < 4; q++) acc[mi][ni][q] = 0.f;

    auto stage = [&](int t) {
        int buf = t % 3;
        int k0 = t * L1_BK;
        cp16(&As[buf][am0 * LDA + ac0 * 4],
             &feat[(size_t)(row0 + am0) * FIN + k0 + ac0 * 4], row0 + am0 < Nn);
        cp16(&As[buf][am1 * LDA + ac0 * 4],
             &feat[(size_t)(row0 + am1) * FIN + k0 + ac0 * 4], row0 + am1 < Nn);
        cp16(&Bs[buf][bk * LDB + bn * 4],
             &W1[(size_t)(k0 + bk) * NHID + bn * 4], true);
        asm volatile("cp.async.commit_group;\n");
    };

    stage(0);
    stage(1);

    for (int t = 0; t < NTILE; t++) {
        if (t + 2 < NTILE) {
            stage(t + 2);
            asm volatile("cp.async.wait_group 2;\n");
        } else if (t + 1 < NTILE) {
            asm volatile("cp.async.wait_group 1;\n");
        } else {
            asm volatile("cp.async.wait_group 0;\n");
        }
        __syncthreads();

        const float* A = As[t % 3];
        const float* B = Bs[t % 3];
#pragma unroll
        for (int kk = 0; kk < L1_BK; kk += 8) {
            unsigned a[2][4], b[4][2];
#pragma unroll
            for (int mi = 0; mi < 2; mi++) {
                int m0 = warp_m * 32 + mi * 16;
                a[mi][0] = f2tf32(A[(m0 + gid)     * LDA + kk + tig]);
                a[mi][1] = f2tf32(A[(m0 + 8 + gid) * LDA + kk + tig]);
                a[mi][2] = f2tf32(A[(m0 + gid)     * LDA + kk + 4 + tig]);
                a[mi][3] = f2tf32(A[(m0 + 8 + gid) * LDA + kk + 4 + tig]);
            }
#pragma unroll
            for (int ni = 0; ni < 4; ni++) {
                int n0 = warp_n * 32 + ni * 8;
                b[ni][0] = f2tf32(B[(kk + tig)     * LDB + n0 + gid]);
                b[ni][1] = f2tf32(B[(kk + 4 + tig) * LDB + n0 + gid]);
            }
#pragma unroll
            for (int mi = 0; mi < 2; mi++)
#pragma unroll
                for (int ni = 0; ni < 4; ni++)
                    mma_tf32(acc[mi][ni], a[mi][0], a[mi][1], a[mi][2], a[mi][3],
                             b[ni][0], b[ni][1]);
        }
        __syncthreads();
    }

#pragma unroll
    for (int mi = 0; mi < 2; mi++) {
        int rbase = row0 + warp_m * 32 + mi * 16 + gid;
#pragma unroll
        for (int ni = 0; ni < 4; ni++) {
            int col = warp_n * 32 + ni * 8 + 2 * tig;
            float bb0 = __ldg(&b1[col]);
            float bb1 = __ldg(&b1[col + 1]);
            if (rbase < Nn) {
                float2 v;
                v.x = fmaxf(acc[mi][ni][0] + bb0, 0.f);
                v.y = fmaxf(acc[mi][ni][1] + bb1, 0.f);
                *(float2*)&g_x1[(size_t)rbase * NHID + col] = v;
            }
            if (rbase + 8 < Nn) {
                float2 v;
                v.x = fmaxf(acc[mi][ni][2] + bb0, 0.f);
                v.y = fmaxf(acc[mi][ni][3] + bb1, 0.f);
                *(float2*)&g_x1[(size_t)(rbase + 8) * NHID + col] = v;
            }
        }
    }
}

// ---------------- layer 2: h = x1 @ W2 + b2 (writes fp32 h AND fp16 y_0) ---
__global__ __launch_bounds__(256)
void mlp2_kernel(const float* __restrict__ W2, const float* __restrict__ b2)
{
    __shared__ float W2s[NHID * NCLS];
    __shared__ float b2s[NCLS];
    int tid = threadIdx.x;
    for (int i = tid; i < NHID * NCLS; i += 256) W2s[i] = W2[i];
    if (tid < NCLS) b2s[tid] = b2[tid];
    __syncthreads();

    int row = blockIdx.x * blockDim.x + tid;
    if (row >= Nn) return;

    float out[NCLS];
#pragma unroll
    for (int c = 0; c < NCLS; c++) out[c] = b2s[c];
    const float* xr = &g_x1[(size_t)row * NHID];
#pragma unroll 4
    for (int k0 = 0; k0 < NHID; k0 += 4) {
        float4 xv = *(const float4*)&xr[k0];
        float xs[4] = {xv.x, xv.y, xv.z, xv.w};
#pragma unroll
        for (int kk = 0; kk < 4; kk++)
#pragma unroll
            for (int c = 0; c < NCLS; c++)
                out[c] = fmaf(xs[kk], W2s[(k0 + kk) * NCLS + c], out[c]);
    }
    float4* hp = g_h + (size_t)row * 10;
#pragma unroll
    for (int q = 0; q < 10; q++)
        hp[q] = make_float4(out[4*q], out[4*q+1], out[4*q+2], out[4*q+3]);
    uint4* yh = g_yh + (size_t)row * 5;
#pragma unroll
    for (int q = 0; q < 5; q++)
        yh[q] = pack8(&out[8 * q]);
}

// ---------------- CSR build ------------------------------------------------
__global__ void zero_kernel()
{
    int i = blockIdx.x * blockDim.x + threadIdx.x;
    if (i < Nn) g_counts[i] = 0;
    if (i < SCAN_NBLK) g_pub[i] = 0ull;
    if (i == 0) g_bar = 0u;
}

__global__ void hist_kernel(const int* __restrict__ rows)
{
    int j = blockIdx.x * blockDim.x + threadIdx.x;
    if (j < Ee / 4) {
        int4 r = ((const int4*)rows)[j];
        atomicAdd(&g_counts[r.x], 1);
        atomicAdd(&g_counts[r.y], 1);
        atomicAdd(&g_counts[r.z], 1);
        atomicAdd(&g_counts[r.w], 1);
    }
}

__global__ __launch_bounds__(SCAN_BLK)
void scan_kernel()
{
    __shared__ int swarp[32];
    __shared__ int s_prefix;
    __shared__ int s_total;

    const int b = blockIdx.x;
    const int t = threadIdx.x;
    const int lane = t & 31, wid = t >> 5;
    const int i = b * SCAN_BLK + t;

    int v = (i < Nn) ? g_counts[i] : 0;
    int incl = v;
#pragma unroll
    for (int off = 1; off < 32; off <<= 1) {
        int u = __shfl_up_sync(0xffffffffu, incl, off);
        if (lane >= off) incl += u;
    }
    if (lane == 31) swarp[wid] = incl;
    __syncthreads();
    if (wid == 0) {
        int w = swarp[lane];
        int wi = w;
#pragma unroll
        for (int off = 1; off < 32; off <<= 1) {
            int u = __shfl_up_sync(0xffffffffu, wi, off);
            if (lane >= off) wi += u;
        }
        swarp[lane] = wi - w;
        if (lane == 31) {
            int S = wi;
            s_total = S;
            if (b == 0) {
                atomicExch(&g_pub[0], (2ull << 32) | (unsigned)S);
                s_prefix = 0;
            } else {
                atomicExch(&g_pub[b], (1ull << 32) | (unsigned)S);
                long long run = 0;
                int p = b - 1;
                while (true) {
                    unsigned long long u =
                        *((volatile unsigned long long*)&g_pub[p]);
                    unsigned f = (unsigned)(u >> 32);
                    if (f == 2u) { run += (int)(unsigned)u; break; }
                    if (f == 1u) { run += (int)(unsigned)u; p--; }
                }
                atomicExch(&g_pub[b], (2ull << 32) | (unsigned)(run + S));
                s_prefix = (int)run;
            }
        }
    }
    __syncthreads();
    int pref = s_prefix;
    if (i < Nn) {
        int r = incl - v + swarp[wid] + pref;
        g_rowptr[i] = r;
        g_cursor[i] = r;
    }
    if (b == SCAN_NBLK - 1 && t == 0)
        g_rowptr[Nn] = pref + s_total;
}

__global__ void scatter_kernel(const int* __restrict__ rows,
                               const int* __restrict__ cols,
                               const float* __restrict__ vals)
{
    int j = blockIdx.x * blockDim.x + threadIdx.x;
    if (j < Ee / 4) {
        int4   r = ((const int4*)rows)[j];
        int4   c = ((const int4*)cols)[j];
        float4 v = ((const float4*)vals)[j];
        int p;
        p = atomicAdd(&g_cursor[r.x], 1); g_colval[p] = make_int2(c.x, __float_as_int(v.x));
        p = atomicAdd(&g_cursor[r.y], 1); g_colval[p] = make_int2(c.y, __float_as_int(v.y));
        p = atomicAdd(&g_cursor[r.z], 1); g_colval[p] = make_int2(c.z, __float_as_int(v.z));
        p = atomicAdd(&g_cursor[r.w], 1); g_colval[p] = make_int2(c.w, __float_as_int(v.w));
    }
}

// ---------------- persistent propagation: steps 0..8, scaled fp16 ----------
// y_{s+1} = (0.9/16) * A * y_s + (0.1/16^{s+1}) * h
__global__ __launch_bounds__(PROP_THREADS, PROP_CO)
void prop_persist_kernel()
{
    const int nthreads = PROP_BLOCKS * PROP_THREADS;
    const int tid0 = blockIdx.x * PROP_THREADS + threadIdx.x;
    const float W = 0.9f / 16.0f;

    for (int s = 0; s < PROP_STEPS; s++) {
        const uint4* __restrict__ yin =
            (s == 0) ? g_yh : ((s & 1) ? g_ya : g_yb);
        uint4* __restrict__ yout = (s & 1) ? g_yb : g_ya;
        const float hc = ldexpf(0.1f, -4 * (s + 1));   // exact 2^-4(s+1) scaling

        for (int t = tid0; t < Nn * 5; t += nthreads) {
            int node = t / 5;
            int g    = t - node * 5;
            float acc[8];
            gather8(yin, g_rowptr[node], g_rowptr[node + 1], g, acc);
            float hf[8];
            unpack8(g_yh[t], hf);
            float o[8];
#pragma unroll
            for (int j = 0; j < 8; j++)
                o[j] = fmaf(W, acc[j], hc * hf[j]);
            yout[t] = pack8(o);
        }

        __threadfence();
        __syncthreads();
        if (threadIdx.x == 0) {
            atomicAdd(&g_bar, 1u);
            unsigned target = (unsigned)(s + 1) * PROP_BLOCKS;
            while (*((volatile unsigned*)&g_bar) < target)
                __nanosleep(64);
        }
        __syncthreads();
        __threadfence();
    }
}

// ---------------- final step (unscale) + fused log_softmax ------------------
__global__ __launch_bounds__(320)
void prop_last_kernel(float* __restrict__ out)
{
    __shared__ float red[320];
    __shared__ float rlse[64];

    const int lt = threadIdx.x;
    const int t  = blockIdx.x * 320 + lt;
    const int node = t / 5;
    const int g    = t - node * 5;
    const int ln   = lt / 5;
    const bool valid = node < Nn;

    float o[8];
    if (valid) {
        float acc[8];
        gather8(g_ya, g_rowptr[node], g_rowptr[node + 1], g, acc);
        const float FINW = 0.9f * 68719476736.0f;   // 0.9 * 16^9
        float4 h0 = g_h[node * 10 + g * 2];
        float4 h1 = g_h[node * 10 + g * 2 + 1];
        float hv[8] = {h0.x, h0.y, h0.z, h0.w, h1.x, h1.y, h1.z, h1.w};
#pragma unroll
        for (int j = 0; j < 8; j++)
            o[j] = fmaf(FINW, acc[j], 0.1f * hv[j]);
    } else {
#pragma unroll
        for (int j = 0; j < 8; j++) o[j] = -INFINITY;
    }

    float lm = o[0];
#pragma unroll
    for (int j = 1; j < 8; j++) lm = fmaxf(lm, o[j]);
    red[lt] = lm;
    __syncthreads();
    if (g == 0) {
        float m = red[ln * 5];
#pragma unroll
        for (int q = 1; q < 5; q++) m = fmaxf(m, red[ln * 5 + q]);
        rlse[ln] = m;
    }
    __syncthreads();
    float m = rlse[ln];

    float s8 = 0.f;
    if (valid) {
#pragma unroll
        for (int j = 0; j < 8; j++) s8 += expf(o[j] - m);
    }
    __syncthreads();
    red[lt] = s8;
    __syncthreads();
    if (g == 0) {
        float s = red[ln * 5];
#pragma unroll
        for (int q = 1; q < 5; q++) s += red[ln * 5 + q];
        rlse[ln] = m + logf(s);
    }
    __syncthreads();

    if (valid) {
        float lse = rlse[ln];
        float4 r0 = make_float4(o[0]-lse, o[1]-lse, o[2]-lse, o[3]-lse);
        float4 r1 = make_float4(o[4]-lse, o[5]-lse, o[6]-lse, o[7]-lse);
        ((float4*)out)[node * 10 + g * 2]     = r0;
        ((float4*)out)[node * 10 + g * 2 + 1] = r1;
    }
}

// ---------------- launch ---------------------------------------------------
static cudaStream_t get_side_stream()
{
    static cudaStream_t s = []() {
        cudaStream_t st;
        cudaStreamCreateWithFlags(&st, cudaStreamNonBlocking);
        return st;
    }();
    return s;
}
static cudaEvent_t get_ev(int which)
{
    static cudaEvent_t e0 = []() {
        cudaEvent_t e; cudaEventCreateWithFlags(&e, cudaEventDisableTiming); return e;
    }();
    static cudaEvent_t e1 = []() {
        cudaEvent_t e; cudaEventCreateWithFlags(&e, cudaEventDisableTiming); return e;
    }();
    return which ? e1 : e0;
}

extern "C" void kernel_launch(void* const* d_in, const int* in_sizes, int n_in,
                              void* d_out, int out_size)
{
    const float* feat = (const float*)d_in[0];
    const int*   ei   = (const int*)  d_in[1];
    const float* ev   = (const float*)d_in[2];
    const float* W1   = (const float*)d_in[3];
    const float* b1   = (const float*)d_in[4];
    const float* W2   = (const float*)d_in[5];
    const float* b2   = (const float*)d_in[6];
    const int* rows = ei;
    const int* cols = ei + Ee;

    cudaStream_t s2 = get_side_stream();
    cudaEvent_t eva = get_ev(0), evb = get_ev(1);

    cudaEventRecord(eva, 0);
    cudaStreamWaitEvent(s2, eva, 0);

    // side stream: CSR build chain
    zero_kernel<<<(Nn + 255) / 256, 256, 0, s2>>>();                 // 1
    hist_kernel<<<(Ee / 4 + 255) / 256, 256, 0, s2>>>(rows);         // 2
    scan_kernel<<<SCAN_NBLK, SCAN_BLK, 0, s2>>>();                   // 3

    // main stream: MLP chain (launch 4 = mlp1, profiled)
    mlp1_kernel<<<(Nn + L1_BM - 1) / L1_BM, 256>>>(feat, W1, b1);    // 4

    scatter_kernel<<<(Ee / 4 + 255) / 256, 256, 0, s2>>>(rows, cols, ev);  // 5

    mlp2_kernel<<<(Nn + 255) / 256, 256>>>(W2, b2);                  // 6

    cudaEventRecord(evb, s2);
    cudaStreamWaitEvent(0, evb, 0);

    // steps 0..8 persistent (scaled fp16, 5 CTAs/SM, dual-acc gather)
    prop_persist_kernel<<<PROP_BLOCKS, PROP_THREADS>>>();

    // final step (unscale) + log_softmax
    prop_last_kernel<<<(Nn * 5 + 319) / 320, 320>>>((float*)d_out);
}

// round 13
// speedup vs baseline: 1.0761x; 1.0121x over previous
#include <cuda_runtime.h>
#include <cuda_fp16.h>
#include <math.h>

#define Nn 100000
#define Ee 3200000
#define FIN 512
#define NHID 64
#define NCLS 40
#define KSTEPS 10

#define PROP_CO 5                       // co-resident CTAs per SM (reg cap 51)
#define PROP_BLOCKS (148 * PROP_CO)     // 740
#define PROP_THREADS 256
#define PROP_STEPS (KSTEPS - 1)         // steps 0..8 in the persistent kernel

#define YSTRIDE 8   // uint4 slots per node row (128B padded; 5 used)

// ---------------- scratch (static device globals — no allocation) ----------
__device__ float4 g_h [Nn * 10];             // teleport term fp32, [N][40]
__device__ uint4  g_yh[Nn * YSTRIDE];        // h in fp16 (= y_0), 128B rows
__device__ uint4  g_ya[Nn * YSTRIDE];        // scaled fp16 iterate ping
__device__ uint4  g_yb[Nn * YSTRIDE];        // scaled fp16 iterate pong
__device__ float  g_x1[(size_t)Nn * NHID];   // layer-1 activations
__device__ int    g_counts[Nn];
__device__ int    g_rowptr[Nn + 1];
__device__ int    g_cursor[Nn];
__device__ int2   g_colval[Ee];              // interleaved {col, val-bits}
__device__ unsigned g_bar;                   // persistent-kernel barrier counter

#define SCAN_BLK  1024
#define SCAN_NBLK ((Nn + SCAN_BLK - 1) / SCAN_BLK)   // 98
__device__ unsigned long long g_pub[SCAN_NBLK];      // packed {flag,sum}

// ---------------- fp16x8 helpers -------------------------------------------
__device__ __forceinline__ void fma8(float* a, float v, uint4 y)
{
    __half2 h0 = *reinterpret_cast<__half2*>(&y.x);
    __half2 h1 = *reinterpret_cast<__half2*>(&y.y);
    __half2 h2 = *reinterpret_cast<__half2*>(&y.z);
    __half2 h3 = *reinterpret_cast<__half2*>(&y.w);
    float2 f0 = __half22float2(h0), f1 = __half22float2(h1);
    float2 f2 = __half22float2(h2), f3 = __half22float2(h3);
    a[0] = fmaf(v, f0.x, a[0]); a[1] = fmaf(v, f0.y, a[1]);
    a[2] = fmaf(v, f1.x, a[2]); a[3] = fmaf(v, f1.y, a[3]);
    a[4] = fmaf(v, f2.x, a[4]); a[5] = fmaf(v, f2.y, a[5]);
    a[6] = fmaf(v, f3.x, a[6]); a[7] = fmaf(v, f3.y, a[7]);
}

__device__ __forceinline__ void unpack8(uint4 y, float* f)
{
    __half2 h0 = *reinterpret_cast<__half2*>(&y.x);
    __half2 h1 = *reinterpret_cast<__half2*>(&y.y);
    __half2 h2 = *reinterpret_cast<__half2*>(&y.z);
    __half2 h3 = *reinterpret_cast<__half2*>(&y.w);
    float2 f0 = __half22float2(h0), f1 = __half22float2(h1);
    float2 f2 = __half22float2(h2), f3 = __half22float2(h3);
    f[0] = f0.x; f[1] = f0.y; f[2] = f1.x; f[3] = f1.y;
    f[4] = f2.x; f[5] = f2.y; f[6] = f3.x; f[7] = f3.y;
}

__device__ __forceinline__ uint4 pack8(const float* f)
{
    __half2 h0 = __floats2half2_rn(f[0], f[1]);
    __half2 h1 = __floats2half2_rn(f[2], f[3]);
    __half2 h2 = __floats2half2_rn(f[4], f[5]);
    __half2 h3 = __floats2half2_rn(f[6], f[7]);
    uint4 r;
    r.x = *reinterpret_cast<unsigned*>(&h0);
    r.y = *reinterpret_cast<unsigned*>(&h1);
    r.z = *reinterpret_cast<unsigned*>(&h2);
    r.w = *reinterpret_cast<unsigned*>(&h3);
    return r;
}

// edge gather over 128B-padded fp16 rows: dual acc + colval prefetch
__device__ __forceinline__ void gather8(const uint4* __restrict__ yin,
                                        int s, int e, int g, float* acc)
{
    float a[8] = {0.f,0.f,0.f,0.f,0.f,0.f,0.f,0.f};
    float b[8] = {0.f,0.f,0.f,0.f,0.f,0.f,0.f,0.f};
    int i = s;
    int2 c0, c1;
    if (i + 2 <= e) {
        c0 = g_colval[i];
        c1 = g_colval[i + 1];
    }
    for (; i + 4 <= e; i += 2) {
        uint4 y0 = __ldg(&yin[(size_t)c0.x * YSTRIDE + g]);
        uint4 y1 = __ldg(&yin[(size_t)c1.x * YSTRIDE + g]);
        int2 n0 = g_colval[i + 2];
        int2 n1 = g_colval[i + 3];
        fma8(a, __int_as_float(c0.y), y0);
        fma8(b, __int_as_float(c1.y), y1);
        c0 = n0; c1 = n1;
    }
    if (i + 2 <= e) {
        uint4 y0 = __ldg(&yin[(size_t)c0.x * YSTRIDE + g]);
        uint4 y1 = __ldg(&yin[(size_t)c1.x * YSTRIDE + g]);
        fma8(a, __int_as_float(c0.y), y0);
        fma8(b, __int_as_float(c1.y), y1);
        i += 2;
    }
    if (i < e) {
        int2 ct = g_colval[i];
        uint4 y0 = __ldg(&yin[(size_t)ct.x * YSTRIDE + g]);
        fma8(a, __int_as_float(ct.y), y0);
    }
#pragma unroll
    for (int j = 0; j < 8; j++) acc[j] = a[j] + b[j];
}

// ---------------- layer 1: x1 = relu(X@W1 + b1) via tf32 mma ---------------
#define L1_BM 128
#define L1_BK 16
#define NTILE (FIN / L1_BK)   // 32
#define LDA   20
#define LDB   72

__device__ __forceinline__ unsigned f2tf32(float f) {
    unsigned r;
    asm("cvt.rna.tf32.f32 %0, %1;" : "=r"(r) : "f"(f));
    return r;
}

__device__ __forceinline__ void mma_tf32(float* c, unsigned a0, unsigned a1,
                                         unsigned a2, unsigned a3,
                                         unsigned b0, unsigned b1) {
    asm volatile(
        "mma.sync.aligned.m16n8k8.row.col.f32.tf32.tf32.f32 "
        "{%0,%1,%2,%3}, {%4,%5,%6,%7}, {%8,%9}, {%0,%1,%2,%3};\n"
        : "+f"(c[0]), "+f"(c[1]), "+f"(c[2]), "+f"(c[3])
        : "r"(a0), "r"(a1), "r"(a2), "r"(a3), "r"(b0), "r"(b1));
}

__device__ __forceinline__ void cp16(float* smem_dst, const float* gsrc, bool pred) {
    unsigned saddr = (unsigned)__cvta_generic_to_shared(smem_dst);
    int sz = pred ? 16 : 0;
    asm volatile("cp.async.cg.shared.global [%0], [%1], 16, %2;\n"
                 :: "r"(saddr), "l"(gsrc), "r"(sz));
}

__global__ __launch_bounds__(256, 3)
void mlp1_kernel(const float* __restrict__ feat,
                 const float* __restrict__ W1, const float* __restrict__ b1)
{
    __shared__ __align__(16) float As[3][L1_BM * LDA];
    __shared__ __align__(16) float Bs[3][L1_BK * LDB];

    const int tid    = threadIdx.x;
    const int lane   = tid & 31;
    const int warp   = tid >> 5;
    const int warp_m = warp & 3;
    const int warp_n = warp >> 2;
    const int gid    = lane >> 2;
    const int tig    = lane & 3;
    const int row0   = blockIdx.x * L1_BM;

    const int am0 = tid >> 2;
    const int ac0 = tid & 3;
    const int am1 = (tid + 256) >> 2;
    const int bk  = tid >> 4;
    const int bn  = tid & 15;

    float acc[2][4][4];
#pragma unroll
    for (int mi = 0; mi < 2; mi++)
#pragma unroll
        for (int ni = 0; ni < 4; ni++)
#pragma unroll
            for (int q = 0; q < 4; q++) acc[mi][ni][q] = 0.f;

    auto stage = [&](int t) {
        int buf = t % 3;
        int k0 = t * L1_BK;
        cp16(&As[buf][am0 * LDA + ac0 * 4],
             &feat[(size_t)(row0 + am0) * FIN + k0 + ac0 * 4], row0 + am0 < Nn);
        cp16(&As[buf][am1 * LDA + ac0 * 4],
             &feat[(size_t)(row0 + am1) * FIN + k0 + ac0 * 4], row0 + am1 < Nn);
        cp16(&Bs[buf][bk * LDB + bn * 4],
             &W1[(size_t)(k0 + bk) * NHID + bn * 4], true);
        asm volatile("cp.async.commit_group;\n");
    };

    stage(0);
    stage(1);

    for (int t = 0; t < NTILE; t++) {
        if (t + 2 < NTILE) {
            stage(t + 2);
            asm volatile("cp.async.wait_group 2;\n");
        } else if (t + 1 < NTILE) {
            asm volatile("cp.async.wait_group 1;\n");
        } else {
            asm volatile("cp.async.wait_group 0;\n");
        }
        __syncthreads();

        const float* A = As[t % 3];
        const float* B = Bs[t % 3];
#pragma unroll
        for (int kk = 0; kk < L1_BK; kk += 8) {
            unsigned a[2][4], b[4][2];
#pragma unroll
            for (int mi = 0; mi < 2; mi++) {
                int m0 = warp_m * 32 + mi * 16;
                a[mi][0] = f2tf32(A[(m0 + gid)     * LDA + kk + tig]);
                a[mi][1] = f2tf32(A[(m0 + 8 + gid) * LDA + kk + tig]);
                a[mi][2] = f2tf32(A[(m0 + gid)     * LDA + kk + 4 + tig]);
                a[mi][3] = f2tf32(A[(m0 + 8 + gid) * LDA + kk + 4 + tig]);
            }
#pragma unroll
            for (int ni = 0; ni < 4; ni++) {
                int n0 = warp_n * 32 + ni * 8;
                b[ni][0] = f2tf32(B[(kk + tig)     * LDB + n0 + gid]);
                b[ni][1] = f2tf32(B[(kk + 4 + tig) * LDB + n0 + gid]);
            }
#pragma unroll
            for (int mi = 0; mi < 2; mi++)
#pragma unroll
                for (int ni = 0; ni < 4; ni++)
                    mma_tf32(acc[mi][ni], a[mi][0], a[mi][1], a[mi][2], a[mi][3],
                             b[ni][0], b[ni][1]);
        }
        __syncthreads();
    }

#pragma unroll
    for (int mi = 0; mi < 2; mi++) {
        int rbase = row0 + warp_m * 32 + mi * 16 + gid;
#pragma unroll
        for (int ni = 0; ni < 4; ni++) {
            int col = warp_n * 32 + ni * 8 + 2 * tig;
            float bb0 = __ldg(&b1[col]);
            float bb1 = __ldg(&b1[col + 1]);
            if (rbase < Nn) {
                float2 v;
                v.x = fmaxf(acc[mi][ni][0] + bb0, 0.f);
                v.y = fmaxf(acc[mi][ni][1] + bb1, 0.f);
                *(float2*)&g_x1[(size_t)rbase * NHID + col] = v;
            }
            if (rbase + 8 < Nn) {
                float2 v;
                v.x = fmaxf(acc[mi][ni][2] + bb0, 0.f);
                v.y = fmaxf(acc[mi][ni][3] + bb1, 0.f);
                *(float2*)&g_x1[(size_t)(rbase + 8) * NHID + col] = v;
            }
        }
    }
}

// ---------------- layer 2: h = x1 @ W2 + b2 (writes fp32 h AND fp16 y_0) ---
__global__ __launch_bounds__(256)
void mlp2_kernel(const float* __restrict__ W2, const float* __restrict__ b2)
{
    __shared__ float W2s[NHID * NCLS];
    __shared__ float b2s[NCLS];
    int tid = threadIdx.x;
    for (int i = tid; i < NHID * NCLS; i += 256) W2s[i] = W2[i];
    if (tid < NCLS) b2s[tid] = b2[tid];
    __syncthreads();

    int row = blockIdx.x * blockDim.x + tid;
    if (row >= Nn) return;

    float out[NCLS];
#pragma unroll
    for (int c = 0; c < NCLS; c++) out[c] = b2s[c];
    const float* xr = &g_x1[(size_t)row * NHID];
#pragma unroll 4
    for (int k0 = 0; k0 < NHID; k0 += 4) {
        float4 xv = *(const float4*)&xr[k0];
        float xs[4] = {xv.x, xv.y, xv.z, xv.w};
#pragma unroll
        for (int kk = 0; kk < 4; kk++)
#pragma unroll
            for (int c = 0; c < NCLS; c++)
                out[c] = fmaf(xs[kk], W2s[(k0 + kk) * NCLS + c], out[c]);
    }
    float4* hp = g_h + (size_t)row * 10;
#pragma unroll
    for (int q = 0; q < 10; q++)
        hp[q] = make_float4(out[4*q], out[4*q+1], out[4*q+2], out[4*q+3]);
    uint4* yh = g_yh + (size_t)row * YSTRIDE;
#pragma unroll
    for (int q = 0; q < 5; q++)
        yh[q] = pack8(&out[8 * q]);
}

// ---------------- CSR build ------------------------------------------------
__global__ void zero_kernel()
{
    int i = blockIdx.x * blockDim.x + threadIdx.x;
    if (i < Nn) g_counts[i] = 0;
    if (i < SCAN_NBLK) g_pub[i] = 0ull;
    if (i == 0) g_bar = 0u;
}

__global__ void hist_kernel(const int* __restrict__ rows)
{
    int j = blockIdx.x * blockDim.x + threadIdx.x;
    if (j < Ee / 4) {
        int4 r = ((const int4*)rows)[j];
        atomicAdd(&g_counts[r.x], 1);
        atomicAdd(&g_counts[r.y], 1);
        atomicAdd(&g_counts[r.z], 1);
        atomicAdd(&g_counts[r.w], 1);
    }
}

__global__ __launch_bounds__(SCAN_BLK)
void scan_kernel()
{
    __shared__ int swarp[32];
    __shared__ int s_prefix;
    __shared__ int s_total;

    const int b = blockIdx.x;
    const int t = threadIdx.x;
    const int lane = t & 31, wid = t >> 5;
    const int i = b * SCAN_BLK + t;

    int v = (i < Nn) ? g_counts[i] : 0;
    int incl = v;
#pragma unroll
    for (int off = 1; off < 32; off <<= 1) {
        int u = __shfl_up_sync(0xffffffffu, incl, off);
        if (lane >= off) incl += u;
    }
    if (lane == 31) swarp[wid] = incl;
    __syncthreads();
    if (wid == 0) {
        int w = swarp[lane];
        int wi = w;
#pragma unroll
        for (int off = 1; off < 32; off <<= 1) {
            int u = __shfl_up_sync(0xffffffffu, wi, off);
            if (lane >= off) wi += u;
        }
        swarp[lane] = wi - w;
        if (lane == 31) {
            int S = wi;
            s_total = S;
            if (b == 0) {
                atomicExch(&g_pub[0], (2ull << 32) | (unsigned)S);
                s_prefix = 0;
            } else {
                atomicExch(&g_pub[b], (1ull << 32) | (unsigned)S);
                long long run = 0;
                int p = b - 1;
                while (true) {
                    unsigned long long u =
                        *((volatile unsigned long long*)&g_pub[p]);
                    unsigned f = (unsigned)(u >> 32);
                    if (f == 2u) { run += (int)(unsigned)u; break; }
                    if (f == 1u) { run += (int)(unsigned)u; p--; }
                }
                atomicExch(&g_pub[b], (2ull << 32) | (unsigned)(run + S));
                s_prefix = (int)run;
            }
        }
    }
    __syncthreads();
    int pref = s_prefix;
    if (i < Nn) {
        int r = incl - v + swarp[wid] + pref;
        g_rowptr[i] = r;
        g_cursor[i] = r;
    }
    if (b == SCAN_NBLK - 1 && t == 0)
        g_rowptr[Nn] = pref + s_total;
}

__global__ void scatter_kernel(const int* __restrict__ rows,
                               const int* __restrict__ cols,
                               const float* __restrict__ vals)
{
    int j = blockIdx.x * blockDim.x + threadIdx.x;
    if (j < Ee / 4) {
        int4   r = ((const int4*)rows)[j];
        int4   c = ((const int4*)cols)[j];
        float4 v = ((const float4*)vals)[j];
        int p;
        p = atomicAdd(&g_cursor[r.x], 1); g_colval[p] = make_int2(c.x, __float_as_int(v.x));
        p = atomicAdd(&g_cursor[r.y], 1); g_colval[p] = make_int2(c.y, __float_as_int(v.y));
        p = atomicAdd(&g_cursor[r.z], 1); g_colval[p] = make_int2(c.z, __float_as_int(v.z));
        p = atomicAdd(&g_cursor[r.w], 1); g_colval[p] = make_int2(c.w, __float_as_int(v.w));
    }
}

// ---------------- persistent propagation: steps 0..8, scaled fp16 ----------
// y_{s+1} = (0.9/16) * A * y_s + (0.1/16^{s+1}) * h
__global__ __launch_bounds__(PROP_THREADS, PROP_CO)
void prop_persist_kernel()
{
    const int nthreads = PROP_BLOCKS * PROP_THREADS;
    const int tid0 = blockIdx.x * PROP_THREADS + threadIdx.x;
    const float W = 0.9f / 16.0f;

    for (int s = 0; s < PROP_STEPS; s++) {
        const uint4* __restrict__ yin =
            (s == 0) ? g_yh : ((s & 1) ? g_ya : g_yb);
        uint4* __restrict__ yout = (s & 1) ? g_yb : g_ya;
        const float hc = ldexpf(0.1f, -4 * (s + 1));   // exact 2^-4(s+1) scaling

        for (int t = tid0; t < Nn * 5; t += nthreads) {
            int node = t / 5;
            int g    = t - node * 5;
            size_t yi = (size_t)node * YSTRIDE + g;
            float acc[8];
            gather8(yin, g_rowptr[node], g_rowptr[node + 1], g, acc);
            float hf[8];
            unpack8(g_yh[yi], hf);
            float o[8];
#pragma unroll
            for (int j = 0; j < 8; j++)
                o[j] = fmaf(W, acc[j], hc * hf[j]);
            yout[yi] = pack8(o);
        }

        __threadfence();
        __syncthreads();
        if (threadIdx.x == 0) {
            atomicAdd(&g_bar, 1u);
            unsigned target = (unsigned)(s + 1) * PROP_BLOCKS;
            while (*((volatile unsigned*)&g_bar) < target)
                __nanosleep(64);
        }
        __syncthreads();
        __threadfence();
    }
}

// ---------------- final step (unscale) + fused log_softmax ------------------
__global__ __launch_bounds__(320)
void prop_last_kernel(float* __restrict__ out)
{
    __shared__ float red[320];
    __shared__ float rlse[64];

    const int lt = threadIdx.x;
    const int t  = blockIdx.x * 320 + lt;
    const int node = t / 5;
    const int g    = t - node * 5;
    const int ln   = lt / 5;
    const bool valid = node < Nn;

    float o[8];
    if (valid) {
        float acc[8];
        gather8(g_ya, g_rowptr[node], g_rowptr[node + 1], g, acc);
        const float FINW = 0.9f * 68719476736.0f;   // 0.9 * 16^9
        float4 h0 = g_h[node * 10 + g * 2];
        float4 h1 = g_h[node * 10 + g * 2 + 1];
        float hv[8] = {h0.x, h0.y, h0.z, h0.w, h1.x, h1.y, h1.z, h1.w};
#pragma unroll
        for (int j = 0; j < 8; j++)
            o[j] = fmaf(FINW, acc[j], 0.1f * hv[j]);
    } else {
#pragma unroll
        for (int j = 0; j < 8; j++) o[j] = -INFINITY;
    }

    float lm = o[0];
#pragma unroll
    for (int j = 1; j < 8; j++) lm = fmaxf(lm, o[j]);
    red[lt] = lm;
    __syncthreads();
    if (g == 0) {
        float m = red[ln * 5];
#pragma unroll
        for (int q = 1; q < 5; q++) m = fmaxf(m, red[ln * 5 + q]);
        rlse[ln] = m;
    }
    __syncthreads();
    float m = rlse[ln];

    float s8 = 0.f;
    if (valid) {
#pragma unroll
        for (int j = 0; j < 8; j++) s8 += expf(o[j] - m);
    }
    __syncthreads();
    red[lt] = s8;
    __syncthreads();
    if (g == 0) {
        float s = red[ln * 5];
#pragma unroll
        for (int q = 1; q < 5; q++) s += red[ln * 5 + q];
        rlse[ln] = m + logf(s);
    }
    __syncthreads();

    if (valid) {
        float lse = rlse[ln];
        float4 r0 = make_float4(o[0]-lse, o[1]-lse, o[2]-lse, o[3]-lse);
        float4 r1 = make_float4(o[4]-lse, o[5]-lse, o[6]-lse, o[7]-lse);
        ((float4*)out)[node * 10 + g * 2]     = r0;
        ((float4*)out)[node * 10 + g * 2 + 1] = r1;
    }
}

// ---------------- launch ---------------------------------------------------
static cudaStream_t get_side_stream()
{
    static cudaStream_t s = []() {
        cudaStream_t st;
        cudaStreamCreateWithFlags(&st, cudaStreamNonBlocking);
        return st;
    }();
    return s;
}
static cudaEvent_t get_ev(int which)
{
    static cudaEvent_t e0 = []() {
        cudaEvent_t e; cudaEventCreateWithFlags(&e, cudaEventDisableTiming); return e;
    }();
    static cudaEvent_t e1 = []() {
        cudaEvent_t e; cudaEventCreateWithFlags(&e, cudaEventDisableTiming); return e;
    }();
    return which ? e1 : e0;
}

extern "C" void kernel_launch(void* const* d_in, const int* in_sizes, int n_in,
                              void* d_out, int out_size)
{
    const float* feat = (const float*)d_in[0];
    const int*   ei   = (const int*)  d_in[1];
    const float* ev   = (const float*)d_in[2];
    const float* W1   = (const float*)d_in[3];
    const float* b1   = (const float*)d_in[4];
    const float* W2   = (const float*)d_in[5];
    const float* b2   = (const float*)d_in[6];
    const int* rows = ei;
    const int* cols = ei + Ee;

    cudaStream_t s2 = get_side_stream();
    cudaEvent_t eva = get_ev(0), evb = get_ev(1);

    cudaEventRecord(eva, 0);
    cudaStreamWaitEvent(s2, eva, 0);

    // side stream: CSR build chain
    zero_kernel<<<(Nn + 255) / 256, 256, 0, s2>>>();                 // 1
    hist_kernel<<<(Ee / 4 + 255) / 256, 256, 0, s2>>>(rows);         // 2
    scan_kernel<<<SCAN_NBLK, SCAN_BLK, 0, s2>>>();                   // 3

    // main stream: MLP chain (launch 4 = mlp1, profiled)
    mlp1_kernel<<<(Nn + L1_BM - 1) / L1_BM, 256>>>(feat, W1, b1);    // 4

    scatter_kernel<<<(Ee / 4 + 255) / 256, 256, 0, s2>>>(rows, cols, ev);  // 5

    mlp2_kernel<<<(Nn + 255) / 256, 256>>>(W2, b2);                  // 6

    cudaEventRecord(evb, s2);
    cudaStreamWaitEvent(0, evb, 0);

    // steps 0..8 persistent (scaled fp16, 128B-padded rows)
    prop_persist_kernel<<<PROP_BLOCKS, PROP_THREADS>>>();

    // final step (unscale) + log_softmax
    prop_last_kernel<<<(Nn * 5 + 319) / 320, 320>>>((float*)d_out);
}